// round 8
// baseline (speedup 1.0000x reference)
#include <cuda_runtime.h>

typedef unsigned long long u64;

#define NK 16
#define TW 136           // tile row stride in floats (col c stores gcol = bx*128 + c - 4)

struct CB {
    u64 crec[NK][16];    // [u[i][j] i=0..3,j=0..2 (x dup), mk, pk, pad, pad]
    float psumh;         // 0.5 * sum(products)
    float pad;
};

__device__   CB g_cb;    // written by setup kernel
__constant__ CB c_cb;    // main kernel reads via uniform const port

__device__ __forceinline__ u64 pack2(float lo, float hi) {
    u64 r; asm("mov.b64 %0, {%1, %2};" : "=l"(r) : "f"(lo), "f"(hi)); return r;
}
__device__ __forceinline__ void unpack2(u64 v, float& lo, float& hi) {
    asm("mov.b64 {%0, %1}, %2;" : "=f"(lo), "=f"(hi) : "l"(v));
}
__device__ __forceinline__ u64 fma2(u64 a, u64 b, u64 c) {
    u64 d; asm("fma.rn.f32x2 %0, %1, %2, %3;" : "=l"(d) : "l"(a), "l"(b), "l"(c)); return d;
}
__device__ __forceinline__ u64 mul2_(u64 a, u64 b) {
    u64 d; asm("mul.rn.f32x2 %0, %1, %2;" : "=l"(d) : "l"(a), "l"(b)); return d;
}
__device__ __forceinline__ u64 add2_(u64 a, u64 b) {
    u64 d; asm("add.rn.f32x2 %0, %1, %2;" : "=l"(d) : "l"(a), "l"(b)); return d;
}
__device__ __forceinline__ u64 sub2_(u64 a, u64 b) {
    u64 d; asm("sub.rn.f32x2 %0, %1, %2;" : "=l"(d) : "l"(a), "l"(b)); return d;
}
__device__ __forceinline__ void tanh2_ip(u64& v) {
    asm("{\n\t"
        ".reg .f32 lo, hi;\n\t"
        "mov.b64 {lo, hi}, %0;\n\t"
        "tanh.approx.f32 lo, lo;\n\t"
        "tanh.approx.f32 hi, hi;\n\t"
        "mov.b64 %0, {lo, hi};\n\t"
        "}" : "+l"(v));
}
__device__ __forceinline__ float addsat_(float a, float b) {
    float r; asm("add.rn.sat.f32 %0, %1, %2;" : "=f"(r) : "f"(a), "f"(b)); return r;
}

// Setup: Winograd F(2,3) weight transform + folded constants (1 block, 256 thr).
// u0 = g0, u1 = (g0+g1+g2)/2, u2 = (g0-g1+g2)/2, u3 = g2  (g = 5*w row)
__global__ void setup_kernel(const float* __restrict__ w,
                             const float* __restrict__ react,
                             const float* __restrict__ prod)
{
    int tid = threadIdx.x;            // 0..255 = NK*16 exactly
    int k = tid >> 4, j16 = tid & 15;
    u64 v = 0ull;
    if (j16 < 12) {
        int i = j16 / 3, jr = j16 - 3 * i;     // m-term i, tap-row jr
        float g0 = 5.0f * w[k * 9 + jr * 3 + 0];
        float g1 = 5.0f * w[k * 9 + jr * 3 + 1];
        float g2 = 5.0f * w[k * 9 + jr * 3 + 2];
        float u;
        if      (i == 0) u = g0;
        else if (i == 1) u = 0.5f * (g0 + g1 + g2);
        else if (i == 2) u = 0.5f * (g0 - g1 + g2);
        else             u = g2;
        v = pack2(u, u);
    } else if (j16 == 12) {
        float t = -5.0f * react[k];            // bias: z = 5N - 5r
        v = pack2(t, t);
    } else if (j16 == 13) {
        float t = 0.5f * prod[k];
        v = pack2(t, t);
    }
    g_cb.crec[k][j16] = v;
    if (tid == 0) {
        float s = 0.0f;
        #pragma unroll
        for (int kk = 0; kk < NK; kk++) s += prod[kk];
        g_cb.psumh = 0.5f * s;
        g_cb.pad = 0.0f;
    }
}

// Grid: (4 col-tiles, 64 row-tiles, 16 batch). Block (64,4) = 256 thr.
// Thread: 2 rows x 2 cols = 4 px. Pairs are VERTICAL (out-row0, out-row1).
__global__ void __launch_bounds__(256, 4)
ca_kernel(const float* __restrict__ x, float* __restrict__ out)
{
    __shared__ __align__(16) float tile[10][TW];   // rows gy0-1 .. gy0+8

    const int bx  = blockIdx.x;
    const int by  = blockIdx.y;
    const int b   = blockIdx.z;
    const int tx  = threadIdx.x;            // 0..63 -> cols 2tx, 2tx+1
    const int ty  = threadIdx.y;            // 0..3  -> rows 2ty, 2ty+1
    const int tid = ty * 64 + tx;

    // ---- tile load: 10 rows x 34 float4 ----
    const float* xb = x + (size_t)b * (512 * 512);
    #pragma unroll
    for (int it = 0; it < 2; it++) {
        int i = tid + it * 256;
        if (i < 340) {
            int r   = i / 34;
            int c4  = i - r * 34;
            int gy  = by * 8 + r - 1;
            int gc0 = bx * 128 + c4 * 4 - 4;
            float4 v = make_float4(0.f, 0.f, 0.f, 0.f);
            if ((unsigned)gy < 512u && (unsigned)gc0 < 512u)
                v = *(const float4*)(xb + (size_t)gy * 512 + gc0);
            *(float4*)&tile[r][c4 * 4] = v;
        }
    }
    __syncthreads();

    // ---- load 4x4 input patch (rows q=0..3, cols gx-1..gx+2) ----
    float d0[4], d1[4], d2[4], d3[4];
    #pragma unroll
    for (int q = 0; q < 4; q++) {
        const float* trow = tile[2 * ty + q];
        d0[q] = trow[2 * tx + 3];
        u64 M = *(const u64*)(trow + 2 * tx + 4);
        unpack2(M, d1[q], d2[q]);
        d3[q] = trow[2 * tx + 6];
    }
    // x centers (vertical pairs): col gx rows (q1,q2); col gx+1 rows (q1,q2)
    const u64 xc0 = pack2(d1[1], d1[2]);
    const u64 xc1 = pack2(d2[1], d2[2]);

    // ---- input Winograd transform, packed over vertical (q, q+1) pairs ----
    // P0 = d0-d2, P1 = d1+d2, P2 = d2-d1, P3 = d1-d3 for j=0..2
    u64 P0[3], P1[3], P2[3], P3[3];
    #pragma unroll
    for (int j = 0; j < 3; j++) {
        u64 V0 = pack2(d0[j], d0[j + 1]);
        u64 V1 = pack2(d1[j], d1[j + 1]);
        u64 V2 = pack2(d2[j], d2[j + 1]);
        u64 V3 = pack2(d3[j], d3[j + 1]);
        P0[j] = sub2_(V0, V2);
        P1[j] = add2_(V1, V2);
        P2[j] = sub2_(V2, V1);
        P3[j] = sub2_(V1, V3);
    }

    u64 aP0 = 0ull, aP1 = 0ull;   // sum(t_k * 0.5 p_k), cols 0/1 (vertical pairs)
    u64 aS0 = 0ull, aS1 = 0ull;   // sum(t_k)

    #pragma unroll
    for (int k = 0; k < NK; k++) {
        const u64* cr = c_cb.crec[k];    // ULDC uniform operands
        const u64 mk  = cr[12];
        const u64 pkk = cr[13];

        // m-accumulators over tap rows (12 FMA2); bias folded into m1
        u64 m0 = mul2_(cr[0], P0[0]);
        u64 m1 = fma2(cr[3], P1[0], mk);
        u64 m2 = mul2_(cr[6], P2[0]);
        u64 m3 = mul2_(cr[9], P3[0]);
        m0 = fma2(cr[1],  P0[1], m0);
        m1 = fma2(cr[4],  P1[1], m1);
        m2 = fma2(cr[7],  P2[1], m2);
        m3 = fma2(cr[10], P3[1], m3);
        m0 = fma2(cr[2],  P0[2], m0);
        m1 = fma2(cr[5],  P1[2], m1);
        m2 = fma2(cr[8],  P2[2], m2);
        m3 = fma2(cr[11], P3[2], m3);

        // output combine (4 ops): zc0 = m0+m1+m2 (col gx), zc1 = m1-m2-m3
        u64 s  = add2_(m1, m2);
        u64 dd = sub2_(m1, m2);
        u64 zc0 = add2_(m0, s);
        u64 zc1 = sub2_(dd, m3);

        tanh2_ip(zc0);
        tanh2_ip(zc1);

        aP0 = fma2(zc0, pkk, aP0);  aS0 = add2_(zc0, aS0);
        aP1 = fma2(zc1, pkk, aP1);  aS1 = add2_(zc1, aS1);
    }

    // ---- epilogue: out = sat( 0.5*sum(p) + aP + x*(-0.5*aS - 7) ) ----
    const float ps = c_cb.psumh;
    const u64 MH2 = pack2(-0.5f, -0.5f);
    const u64 M72 = pack2(-7.0f, -7.0f);

    u64 o0 = fma2(xc0, fma2(aS0, MH2, M72), aP0);   // col gx,   rows (0,1)
    u64 o1 = fma2(xc1, fma2(aS1, MH2, M72), aP1);   // col gx+1, rows (0,1)
    float a0, a1, b0, b1;
    unpack2(o0, a0, a1);    // a0 = row0 col0, a1 = row1 col0
    unpack2(o1, b0, b1);    // b0 = row0 col1, b1 = row1 col1

    const int gy0 = by * 8 + 2 * ty;
    float* ob = out + (size_t)b * (512 * 512) + (size_t)gy0 * 512 + bx * 128 + 2 * tx;
    *(float2*)ob         = make_float2(addsat_(a0, ps), addsat_(b0, ps));
    *(float2*)(ob + 512) = make_float2(addsat_(a1, ps), addsat_(b1, ps));
}

extern "C" void kernel_launch(void* const* d_in, const int* in_sizes, int n_in,
                              void* d_out, int out_size) {
    const float* x = (const float*)d_in[0];
    const float* w = (const float*)d_in[1];
    const float* r = (const float*)d_in[2];
    const float* p = (const float*)d_in[3];

    // 1) Winograd weight transform + constants into g_cb
    setup_kernel<<<1, 256>>>(w, r, p);

    // 2) D2D copy into __constant__ (graph-capturable memcpy node)
    void* gsym = nullptr;
    cudaGetSymbolAddress(&gsym, g_cb);
    cudaMemcpyToSymbolAsync(c_cb, gsym, sizeof(CB), 0, cudaMemcpyDeviceToDevice, 0);

    // 3) main kernel
    dim3 grid(4, 64, 16);
    dim3 block(64, 4);
    ca_kernel<<<grid, block>>>(x, (float*)d_out);
}